// round 5
// baseline (speedup 1.0000x reference)
#include <cuda_runtime.h>

// ASTGC_37976100831379 — R3 (R2 re-bench; prior round hit a container
// infrastructure failure, the kernel itself never executed)
//
// Dead-graph analysis (verified R1, rel_err=0.0): the reference returns
// fusion_out[:, 0], the star-graph hub node, which receives no messages; its
// row of the concat is an explicit zeros tensor. So
//
//     out[b, s, 0] = fgcn_b[s]      b in [0,32), s in [0,48)
//
// i.e. a 48-float -> 1536-float broadcast. Vectorized to float4 (48 % 4 == 0),
// single 384-thread block. Per thread: one LDG.128 from one of 12 distinct
// addresses (maximal L1 sector merge) + one STG.128.

#define ASTGC_S 48
#define TOTAL_F4 384u   // (32*48)/4

__global__ void __launch_bounds__(384, 1)
astgc_bias_broadcast_v4(const float4* __restrict__ bias4,
                        float4* __restrict__ out4) {
    unsigned i = threadIdx.x;       // single block of TOTAL_F4 threads
    // out float4 index i covers floats [4i, 4i+4); since 48 % 4 == 0,
    // source is bias4[i % 12] (unsigned -> magic-multiply, no div pipe).
    out4[i] = bias4[i % 12u];
}

extern "C" void kernel_launch(void* const* d_in, const int* in_sizes, int n_in,
                              void* d_out, int out_size) {
    // Locate fgcn_b: the unique input with exactly S=48 elements.
    int bias_idx = -1;
    for (int i = 0; i < n_in; ++i) {
        if (in_sizes[i] == ASTGC_S) { bias_idx = i; break; }
    }
    if (bias_idx < 0) bias_idx = 30;  // setup_inputs order fallback

    const float4* bias4 = (const float4*)d_in[bias_idx];
    float4* out4 = (float4*)d_out;

    astgc_bias_broadcast_v4<<<1, TOTAL_F4>>>(bias4, out4);
}

// round 8
// speedup vs baseline: 1.3775x; 1.3775x over previous
#include <cuda_runtime.h>

// ASTGC_37976100831379 — R4
//
// Dead-graph analysis (verified R1, rel_err=0.0): the reference returns
// fusion_out[:, 0], the star-graph hub node, which receives no messages
// (its concat row is an explicit zeros tensor). So
//
//     out[b, s, 0] = fgcn_b[s]      b in [0,32), s in [0,48)
//
// -> a 48-float broadcast into [32,48]. R4 = R1's multi-block shape (overlap
// cold-miss latency across SMs; single-block R3 regressed) + float4 vector
// accesses + zero address arithmetic on the load path:
//   block (12, 8): tx = float4 column 0..11, (bx*8+ty) = batch row.
//   load  bias4[tx]            (12 distinct addrs, fully merged in L1/L2)
//   store out4[row*12 + tx]    (warp = 512 contiguous bytes)

#define ASTGC_S 48

__global__ void __launch_bounds__(96, 1)
astgc_bias_broadcast_r4(const float4* __restrict__ bias4,
                        float4* __restrict__ out4) {
    unsigned tx  = threadIdx.x;                       // 0..11  (float4 col)
    unsigned row = blockIdx.x * blockDim.y + threadIdx.y;  // 0..31 (batch)
    out4[row * 12u + tx] = bias4[tx];
}

extern "C" void kernel_launch(void* const* d_in, const int* in_sizes, int n_in,
                              void* d_out, int out_size) {
    // Locate fgcn_b: the unique input with exactly S=48 elements.
    int bias_idx = -1;
    for (int i = 0; i < n_in; ++i) {
        if (in_sizes[i] == ASTGC_S) { bias_idx = i; break; }
    }
    if (bias_idx < 0) bias_idx = 30;  // setup_inputs order fallback

    const float4* bias4 = (const float4*)d_in[bias_idx];
    float4* out4 = (float4*)d_out;

    dim3 block(12, 8);   // 96 threads
    dim3 grid(4);        // 4 * 8 = 32 batch rows
    astgc_bias_broadcast_r4<<<grid, block>>>(bias4, out4);
}

// round 9
// speedup vs baseline: 1.4444x; 1.0486x over previous
#include <cuda_runtime.h>

// ASTGC_37976100831379 — R5
//
// Dead-graph analysis (verified R1, rel_err=0.0 bitwise): the reference
// returns fusion_out[:, 0], the star-graph hub node, which receives no
// messages (its concat row is an explicit zeros tensor). So
//
//     out[b, s, 0] = fgcn_b[s]      b in [0,32), s in [0,48)
//
// -> a 48-float broadcast into [32,48] (6 KB). All throughput metrics are
// ~0%; measured time is launch ramp + cold-miss latency + drain. R5 widens
// CTA dispatch to 8 blocks (overlap the per-CTA cold bias miss across more
// SMs — R1's wider grid had the best kernel time), keeps float4 accesses and
// a zero-arithmetic load path.
//   block (12, 4): tx = float4 column 0..11, (bx*4+ty) = batch row 0..31.
//   load  bias4[tx]           (12 distinct addrs, fully merged)
//   store out4[row*12 + tx]   (contiguous per warp)

#define ASTGC_S 48

__global__ void __launch_bounds__(48, 1)
astgc_bias_broadcast_r5(const float4* __restrict__ bias4,
                        float4* __restrict__ out4) {
    unsigned tx  = threadIdx.x;                            // 0..11 (float4 col)
    unsigned row = blockIdx.x * blockDim.y + threadIdx.y;  // 0..31 (batch)
    out4[row * 12u + tx] = bias4[tx];
}

extern "C" void kernel_launch(void* const* d_in, const int* in_sizes, int n_in,
                              void* d_out, int out_size) {
    // Locate fgcn_b: the unique input with exactly S=48 elements.
    int bias_idx = -1;
    for (int i = 0; i < n_in; ++i) {
        if (in_sizes[i] == ASTGC_S) { bias_idx = i; break; }
    }
    if (bias_idx < 0) bias_idx = 30;  // setup_inputs order fallback

    const float4* bias4 = (const float4*)d_in[bias_idx];
    float4* out4 = (float4*)d_out;

    dim3 block(12, 4);   // 48 threads
    dim3 grid(8);        // 8 * 4 = 32 batch rows
    astgc_bias_broadcast_r5<<<grid, block>>>(bias4, out4);
}